// round 17
// baseline (speedup 1.0000x reference)
#include <cuda_runtime.h>
#include <cuda_bf16.h>
#include <cstdint>

// ---------------- problem constants ----------------
#define N_TOT 8192
#define D     128
#define IPC_C 512
#define ROW0  7680            // bz - IPC
#define NCOL  7680            // unmasked columns [0, 7680)
#define BM    128
#define BN    256
#define NTIL  (NCOL / BN)     // 30 column tiles
#define NBLK  (NTIL * (IPC_C / BM))   // 120 GEMM blocks = one wave
#define NGRP  (NCOL / 8)      // 960 8-col groups; groups [0,128) = easy
#define LDQ   36              // smem row stride in u32 (144 B)
#define WINDW 0.02f           // int8-vs-fp32 dot error window (~17 sigma)

// ---------------- device globals ----------------
__device__ float    g_inv[N_TOT];            // inverse norms (exact fp32)
__device__ uint32_t g_q8[N_TOT * 32];        // normalized rows, int8 x4 packed
__device__ float    g_sub[IPC_C * NGRP];     // per-(row, 8col-group) approx max
__device__ float    g_bpart[16];             // refine per-block loss partials
__device__ int      g_done;                  // zero-init; reset each replay

#define CP_ASYNC16(dst_u32, src_ptr) \
    asm volatile("cp.async.cg.shared.global [%0], [%1], 16;" \
                 :: "r"(dst_u32), "l"(src_ptr) : "memory")
#define CP_COMMIT()  asm volatile("cp.async.commit_group;" ::: "memory")
#define CP_WAIT0()   asm volatile("cp.async.wait_group 0;" ::: "memory")

// ---------------- kernel 1: normalize -> int8 + inv norms (2 rows/warp) ----------------
__global__ void __launch_bounds__(256) prep_kernel(const float* __restrict__ f) {
    const int lane = threadIdx.x & 31;
    const int w    = threadIdx.x >> 5;
    const int r0   = blockIdx.x * 16 + w * 2;

    float4 v0 = ((const float4*)(f + (size_t)r0 * D))[lane];
    float4 v1 = ((const float4*)(f + (size_t)(r0 + 1) * D))[lane];
    float s0 = v0.x * v0.x + v0.y * v0.y + v0.z * v0.z + v0.w * v0.w;
    float s1 = v1.x * v1.x + v1.y * v1.y + v1.z * v1.z + v1.w * v1.w;
    #pragma unroll
    for (int o = 16; o; o >>= 1) {
        s0 += __shfl_xor_sync(0xffffffffu, s0, o);
        s1 += __shfl_xor_sync(0xffffffffu, s1, o);
    }
    float i0 = rsqrtf(s0); if (!(s0 > 1e-24f)) i0 = 1e12f;
    float i1 = rsqrtf(s1); if (!(s1 > 1e-24f)) i1 = 1e12f;
    if (lane == 0) { g_inv[r0] = i0; g_inv[r0 + 1] = i1; }

    float q0 = i0 * 127.f, q1 = i1 * 127.f;
    int a0 = __float2int_rn(v0.x * q0), a1 = __float2int_rn(v0.y * q0);
    int a2 = __float2int_rn(v0.z * q0), a3 = __float2int_rn(v0.w * q0);
    int b0 = __float2int_rn(v1.x * q1), b1 = __float2int_rn(v1.y * q1);
    int b2 = __float2int_rn(v1.z * q1), b3 = __float2int_rn(v1.w * q1);
    g_q8[(size_t)r0 * 32 + lane] =
        (uint32_t)(a0 & 255) | ((uint32_t)(a1 & 255) << 8) |
        ((uint32_t)(a2 & 255) << 16) | ((uint32_t)(a3 & 255) << 24);
    g_q8[(size_t)(r0 + 1) * 32 + lane] =
        (uint32_t)(b0 & 255) | ((uint32_t)(b1 & 255) << 8) |
        ((uint32_t)(b2 & 255) << 16) | ((uint32_t)(b3 & 255) << 24);
}

// ---------------- kernel 2: int8 m16n8k32 GEMM + per-8col-group max ----------------
// 512 threads = 16 warps (4m x 4n); warp tile 32x64; 120 blocks = one wave.
// smem: A s8[128][144B] + B s8[256][144B] = 55296 B
#define SMEM_BYTES ((BM + BN) * LDQ * 4)

__global__ void __launch_bounds__(512, 1) gemm_kernel() {
    extern __shared__ char smraw[];
    uint32_t* Aq = (uint32_t*)smraw;       // [128][36]
    uint32_t* Bq = Aq + BM * LDQ;          // [256][36]

    const int tid  = threadIdx.x;
    const int lane = tid & 31;
    const int w    = tid >> 5;
    const int wm   = w >> 2;        // 0..3 -> 32-row strip
    const int wn   = w & 3;         // 0..3 -> 64-col strip
    const int q    = lane >> 2;     // 0..7
    const int tig  = lane & 3;      // 0..3
    const int rowBase = ROW0 + blockIdx.y * BM;
    const int colBase = blockIdx.x * BN;

    const uint32_t sA = (uint32_t)__cvta_generic_to_shared(Aq);
    const uint32_t sB = (uint32_t)__cvta_generic_to_shared(Bq);

    // ---- stage A (128 rows x 8 chunks) and B (256 rows x 8 chunks) of 16B ----
    #pragma unroll
    for (int t = 0; t < 2; t++) {
        int idx = tid + t * 512;
        int r = idx >> 3, c = idx & 7;
        CP_ASYNC16(sA + r * (LDQ * 4) + c * 16,
                   g_q8 + (size_t)(rowBase + r) * 32 + c * 4);
    }
    #pragma unroll
    for (int t = 0; t < 4; t++) {
        int idx = tid + t * 512;
        int r = idx >> 3, c = idx & 7;
        CP_ASYNC16(sB + r * (LDQ * 4) + c * 16,
                   g_q8 + (size_t)(colBase + r) * 32 + c * 4);
    }
    CP_COMMIT();
    CP_WAIT0();
    __syncthreads();

    int acc[2][8][4];
    #pragma unroll
    for (int mt = 0; mt < 2; mt++)
        #pragma unroll
        for (int nt = 0; nt < 8; nt++)
            #pragma unroll
            for (int e = 0; e < 4; e++) acc[mt][nt][e] = 0;

    const int rA0 = wm * 32 + q;
    const int rB0 = wn * 64 + q;

    #pragma unroll
    for (int s = 0; s < 4; s++) {            // 4 K-steps of k32
        const int ko = s * 8 + tig;
        uint32_t af[2][4];
        #pragma unroll
        for (int mt = 0; mt < 2; mt++) {
            int b0 = (rA0 + mt * 16) * LDQ + ko;
            af[mt][0] = Aq[b0];
            af[mt][1] = Aq[b0 + 8 * LDQ];
            af[mt][2] = Aq[b0 + 4];
            af[mt][3] = Aq[b0 + 8 * LDQ + 4];
        }
        uint32_t bf[8][2];
        #pragma unroll
        for (int nt = 0; nt < 8; nt++) {
            int b0 = (rB0 + nt * 8) * LDQ + ko;
            bf[nt][0] = Bq[b0];
            bf[nt][1] = Bq[b0 + 4];
        }
        #pragma unroll
        for (int mt = 0; mt < 2; mt++)
            #pragma unroll
            for (int nt = 0; nt < 8; nt++)
                asm volatile(
                    "mma.sync.aligned.m16n8k32.row.col.s32.s8.s8.s32 "
                    "{%0,%1,%2,%3}, {%4,%5,%6,%7}, {%8,%9}, {%0,%1,%2,%3};"
                    : "+r"(acc[mt][nt][0]), "+r"(acc[mt][nt][1]),
                      "+r"(acc[mt][nt][2]), "+r"(acc[mt][nt][3])
                    : "r"(af[mt][0]), "r"(af[mt][1]), "r"(af[mt][2]), "r"(af[mt][3]),
                      "r"(bf[nt][0]), "r"(bf[nt][1]));
    }
    __syncthreads();   // all smem reads done before reuse

    // ---- per-(row, 8col-group) max (int domain), tig-reduced, into smem ----
    int* pm = (int*)smraw;    // [128][32]
    #pragma unroll
    for (int mt = 0; mt < 2; mt++)
        #pragma unroll
        for (int nt = 0; nt < 8; nt++) {
            int vlo = max(acc[mt][nt][0], acc[mt][nt][1]);  // row q
            int vhi = max(acc[mt][nt][2], acc[mt][nt][3]);  // row q+8
            #pragma unroll
            for (int o = 1; o < 4; o <<= 1) {
                vlo = max(vlo, __shfl_xor_sync(0xffffffffu, vlo, o));
                vhi = max(vhi, __shfl_xor_sync(0xffffffffu, vhi, o));
            }
            if (tig == 0) {
                int g = wn * 8 + nt;
                int r = wm * 32 + mt * 16 + q;
                pm[r * 32 + g]       = vlo;
                pm[(r + 8) * 32 + g] = vhi;
            }
        }
    __syncthreads();

    // ---- coalesced write: g_sub[row][group], scaled to cosine domain ----
    {
        const float sc = 1.0f / 16129.0f;     // 1/127^2
        int row = tid >> 2, g0 = (tid & 3) * 8;
        float v[8];
        #pragma unroll
        for (int j = 0; j < 8; j++) v[j] = (float)pm[row * 32 + g0 + j] * sc;
        size_t dst = (size_t)(blockIdx.y * BM + row) * NGRP + blockIdx.x * 32 + g0;
        *(float4*)(g_sub + dst)     = make_float4(v[0], v[1], v[2], v[3]);
        *(float4*)(g_sub + dst + 4) = make_float4(v[4], v[5], v[6], v[7]);
    }
}

// ---------------- kernel 3: exact fp32 refine + loss (R7-proven logic) ----------------
// 16 blocks x 1024 threads; one warp per row.
__global__ void __launch_bounds__(1024) refine_kernel(const float* __restrict__ fvec,
                                                      const float* __restrict__ a_scl,
                                                      float* __restrict__ out) {
    __shared__ float red[32];
    const int tid  = threadIdx.x;
    const int lane = tid & 31;
    const int wid  = tid >> 5;
    const int r    = blockIdx.x * 32 + wid;       // 0..511
    const float* sub = g_sub + (size_t)r * NGRP;

    // pass 1: approx class maxima (groups lane+32j; j<4 -> easy cols [0,1024))
    float emax = -2.f, hmax = -2.f;
    #pragma unroll
    for (int j = 0; j < 30; j++) {
        float v = sub[lane + 32 * j];
        if (j < 4) emax = fmaxf(emax, v); else hmax = fmaxf(hmax, v);
    }
    #pragma unroll
    for (int o = 16; o; o >>= 1) {
        emax = fmaxf(emax, __shfl_xor_sync(0xffffffffu, emax, o));
        hmax = fmaxf(hmax, __shfl_xor_sync(0xffffffffu, hmax, o));
    }

    // pass 2: exact fp32 recompute of every group within the window
    const float inv_r = g_inv[ROW0 + r];
    const float4* R4 = (const float4*)(fvec + (size_t)(ROW0 + r) * D);
    float eEx = -2.f, hEx = -2.f;
    #pragma unroll 1
    for (int j = 0; j < 30; j++) {
        float v = sub[lane + 32 * j];
        bool easy = (j < 4);
        float thr = (easy ? emax : hmax) - WINDW;
        unsigned m = __ballot_sync(0xffffffffu, v >= thr);
        while (m) {
            int l = __ffs(m) - 1; m &= m - 1;
            int g = l + 32 * j;
            int c = g * 8 + (lane & 7);
            int seg = lane >> 3;
            const float4* C4 = (const float4*)(fvec + (size_t)c * D);
            float p = 0.f;
            #pragma unroll
            for (int t = 0; t < 8; t++) {
                float4 x = R4[seg * 8 + t];
                float4 y = C4[seg * 8 + t];
                p = fmaf(x.x, y.x, p); p = fmaf(x.y, y.y, p);
                p = fmaf(x.z, y.z, p); p = fmaf(x.w, y.w, p);
            }
            p += __shfl_xor_sync(0xffffffffu, p, 8);
            p += __shfl_xor_sync(0xffffffffu, p, 16);
            float d = p * inv_r * g_inv[c];
            #pragma unroll
            for (int o = 1; o < 8; o <<= 1)
                d = fmaxf(d, __shfl_xor_sync(0xffffffffu, d, o));
            if (easy) eEx = fmaxf(eEx, d); else hEx = fmaxf(hEx, d);
        }
    }

    if (lane == 0) red[wid] = log1pf(expf((hEx - eEx) * 10.0f));  // 1/SIGMA1 = 10
    __syncthreads();

    if (tid == 0) {
        float s = 0.f;
        #pragma unroll
        for (int i = 0; i < 32; i++) s += red[i];
        g_bpart[blockIdx.x] = s;
        __threadfence();
        if (atomicAdd(&g_done, 1) == 15) {
            __threadfence();
            float tot = 0.f;
            #pragma unroll
            for (int i = 0; i < 16; i++) tot += g_bpart[i];
            out[0] = a_scl[0] * tot * (1.0f / 512.0f);
            g_done = 0;
        }
    }
}

extern "C" void kernel_launch(void* const* d_in, const int* in_sizes, int n_in,
                              void* d_out, int out_size) {
    const float* fvec = (const float*)d_in[0];   // [8192,128] f32
    // d_in[1] = Lvec (dead in the reference math)
    const float* a    = (const float*)d_in[2];   // scalar f32
    float* out = (float*)d_out;

    cudaFuncSetAttribute(gemm_kernel,
                         cudaFuncAttributeMaxDynamicSharedMemorySize, SMEM_BYTES);

    prep_kernel<<<N_TOT / 16, 256>>>(fvec);
    gemm_kernel<<<dim3(NTIL, IPC_C / BM), 512, SMEM_BYTES>>>();
    refine_kernel<<<16, 1024>>>(fvec, a, out);
}